// round 3
// baseline (speedup 1.0000x reference)
#include <cuda_runtime.h>

#define NN 100000
#define NE 1600000
#define NP 500000
#define D  128
#define BP 132   // smem pitch

// ---------------- scratch (static device memory; no allocations) ----------------
__device__ int   g_cnt[NN];
__device__ int   g_rowptr[NN + 1];
__device__ int   g_pos[NN];
__device__ float g_inv[NN];
__device__ int   g_srcs[NE];
__device__ float g_aggr[(size_t)NN * D];
__device__ float g_h[(size_t)NN * D];
__device__ float g_z[(size_t)NN * D];
__device__ float g_wt1[256 * 128];   // [Wl|Wr] layer1, k-major: [k][j]
__device__ float g_wt2[256 * 128];   // layer2
__device__ float g_wtm1[128 * 128];  // Wm1 k-major
__device__ float g_wtm2[128 * 64];   // Wm2 k-major

// ---------------- CSR build ----------------
__global__ void k_zero() {
    int i = blockIdx.x * blockDim.x + threadIdx.x;
    if (i < NN) g_cnt[i] = 0;
}

__global__ void k_count(const int* __restrict__ ei) {
    int i = blockIdx.x * blockDim.x + threadIdx.x;
    if (i < NE) atomicAdd(&g_cnt[ei[NE + i]], 1);
}

__global__ void k_scan() {
    __shared__ int s[1024];
    int tid = threadIdx.x;
    int base = 0;
    for (int start = 0; start < NN; start += 1024) {
        int i = start + tid;
        int v = (i < NN) ? g_cnt[i] : 0;
        s[tid] = v;
        __syncthreads();
        for (int off = 1; off < 1024; off <<= 1) {
            int t = (tid >= off) ? s[tid - off] : 0;
            __syncthreads();
            s[tid] += t;
            __syncthreads();
        }
        int excl = base + s[tid] - v;
        if (i < NN) {
            g_rowptr[i] = excl;
            g_pos[i]    = excl;
            g_inv[i]    = 1.0f / (float)(v > 0 ? v : 1);
        }
        base += s[1023];
        __syncthreads();
    }
    if (tid == 0) g_rowptr[NN] = base;
}

__global__ void k_scatter(const int* __restrict__ ei) {
    int i = blockIdx.x * blockDim.x + threadIdx.x;
    if (i < NE) {
        int dst = ei[NE + i];
        int src = ei[i];
        int p = atomicAdd(&g_pos[dst], 1);
        g_srcs[p] = src;
    }
}

// ---------------- weight transpose (once per launch, tiny) ----------------
__global__ void k_wt(const float* __restrict__ W1l, const float* __restrict__ W1r,
                     const float* __restrict__ W2l, const float* __restrict__ W2r,
                     const float* __restrict__ Wm1, const float* __restrict__ Wm2) {
    int i = blockIdx.x * blockDim.x + threadIdx.x;
    if (i < 256 * 128) {
        int k = i >> 7, j = i & 127;
        g_wt1[i] = (k < 128) ? W1l[j * 128 + k] : W1r[j * 128 + (k - 128)];
        g_wt2[i] = (k < 128) ? W2l[j * 128 + k] : W2r[j * 128 + (k - 128)];
    }
    if (i < 128 * 128) {
        int k = i >> 7, j = i & 127;
        g_wtm1[i] = Wm1[j * 128 + k];
    }
    if (i < 128 * 64) {
        int k = i >> 6, j = i & 63;
        g_wtm2[i] = Wm2[j * 128 + k];
    }
}

// ---------------- mean aggregation (CSR, one warp per node) ----------------
__global__ void k_aggr(const float* __restrict__ x, int layer) {
    const float* __restrict__ feat = (layer == 1) ? x : g_h;
    int warp = (blockIdx.x * blockDim.x + threadIdx.x) >> 5;
    int lane = threadIdx.x & 31;
    if (warp >= NN) return;
    int beg = g_rowptr[warp], end = g_rowptr[warp + 1];
    float4 acc = make_float4(0.f, 0.f, 0.f, 0.f);
    for (int e = beg; e < end; e++) {
        int s = g_srcs[e];
        float4 v = *(const float4*)&feat[(size_t)s * D + lane * 4];
        acc.x += v.x; acc.y += v.y; acc.z += v.z; acc.w += v.w;
    }
    float inv = g_inv[warp];
    acc.x *= inv; acc.y *= inv; acc.z *= inv; acc.w *= inv;
    *(float4*)&g_aggr[(size_t)warp * D + lane * 4] = acc;
}

// ---------------- layer GEMM: out = relu?(aggr@Wl^T + b + self@Wr^T) ----------------
// M=100000, N=128, K=256 ([aggr k0..127 | self k128..255]), 128x128 tile, 8x8 micro
__global__ void __launch_bounds__(256, 1)
k_gemm_layer(const float* __restrict__ x, const float* __restrict__ bias, int layer) {
    extern __shared__ float sm[];
    float* Bs = sm;               // [256][BP]
    float* As = sm + 256 * BP;    // [32][BP]  (k-major: As[k][row])

    const float* __restrict__ Aself = (layer == 1) ? x : g_h;
    const float* __restrict__ Wt    = (layer == 1) ? g_wt1 : g_wt2;
    float* __restrict__ out         = (layer == 1) ? g_h : g_z;
    const int do_relu = (layer == 1);

    int tid = threadIdx.x;
    int tx = tid & 15, ty = tid >> 4;
    int row0 = blockIdx.x * 128;

    // weights -> smem (coalesced global, conflict-free STS)
    for (int idx = tid * 4; idx < 256 * 128; idx += 256 * 4) {
        int k = idx >> 7, j = idx & 127;
        *(float4*)&Bs[k * BP + j] = *(const float4*)&Wt[idx];
    }
    float bj[8];
#pragma unroll
    for (int j = 0; j < 8; j++) bj[j] = bias[tx * 8 + j];

    float acc[8][8];
#pragma unroll
    for (int i = 0; i < 8; i++)
#pragma unroll
        for (int j = 0; j < 8; j++) acc[i][j] = 0.f;

    __syncthreads();

    for (int kk = 0; kk < 256; kk += 32) {
        const float* __restrict__ A = (kk < 128) ? g_aggr : Aself;
        int kb = kk & 127;
#pragma unroll
        for (int l = 0; l < 4; l++) {
            int idx = tid + l * 256;        // 0..1023
            int r = idx >> 3, kq = idx & 7; // k offset = kq*4
            int row = row0 + r;
            float4 v = make_float4(0.f, 0.f, 0.f, 0.f);
            if (row < NN) v = *(const float4*)&A[(size_t)row * 128 + kb + kq * 4];
            As[(kq * 4 + 0) * BP + r] = v.x;
            As[(kq * 4 + 1) * BP + r] = v.y;
            As[(kq * 4 + 2) * BP + r] = v.z;
            As[(kq * 4 + 3) * BP + r] = v.w;
        }
        __syncthreads();
#pragma unroll 8
        for (int k = 0; k < 32; k++) {
            float4 a0 = *(float4*)&As[k * BP + ty * 8];
            float4 a1 = *(float4*)&As[k * BP + ty * 8 + 4];
            float4 b0 = *(float4*)&Bs[(kk + k) * BP + tx * 8];
            float4 b1 = *(float4*)&Bs[(kk + k) * BP + tx * 8 + 4];
            float a[8] = {a0.x, a0.y, a0.z, a0.w, a1.x, a1.y, a1.z, a1.w};
            float b[8] = {b0.x, b0.y, b0.z, b0.w, b1.x, b1.y, b1.z, b1.w};
#pragma unroll
            for (int i = 0; i < 8; i++)
#pragma unroll
                for (int j = 0; j < 8; j++) acc[i][j] += a[i] * b[j];
        }
        __syncthreads();
    }

#pragma unroll
    for (int i = 0; i < 8; i++) {
        int row = row0 + ty * 8 + i;
        if (row < NN) {
            float o[8];
#pragma unroll
            for (int j = 0; j < 8; j++) {
                float v = acc[i][j] + bj[j];
                o[j] = do_relu ? fmaxf(v, 0.f) : v;
            }
            *(float4*)&out[(size_t)row * 128 + tx * 8]     = make_float4(o[0], o[1], o[2], o[3]);
            *(float4*)&out[(size_t)row * 128 + tx * 8 + 4] = make_float4(o[4], o[5], o[6], o[7]);
        }
    }
}

// ---------------- fused decoder: 128 pairs/block ----------------
__global__ void __launch_bounds__(256, 1)
k_decoder(const int* __restrict__ pairs,
          const float* __restrict__ bm1g, const float* __restrict__ bm2g,
          const float* __restrict__ wm3g, const float* __restrict__ bm3g,
          float* __restrict__ out) {
    extern __shared__ float sm[];
    float* HP  = sm;                    // [128][BP] stage1: hp k-major; stage2: t1 p-major
    float* W1s = sm + 128 * BP;         // [128][BP] Wm1 k-major
    float* W2s = W1s + 128 * BP;        // [128][64] Wm2 k-major
    float* w3s = W2s + 128 * 64;        // [64]

    int tid = threadIdx.x;
    int tx = tid & 15, ty = tid >> 4;
    int p0 = blockIdx.x * 128;

    for (int idx = tid * 4; idx < 128 * 128; idx += 256 * 4) {
        int k = idx >> 7, j = idx & 127;
        *(float4*)&W1s[k * BP + j] = *(const float4*)&g_wtm1[idx];
    }
    for (int idx = tid * 4; idx < 128 * 64; idx += 256 * 4) {
        *(float4*)&W2s[idx] = *(const float4*)&g_wtm2[idx];
    }
    if (tid < 64) w3s[tid] = wm3g[tid];

    // stage A: hp[k][p] = z[i0][k] * z[i1][k]  (transposed into smem)
    {
        int p  = tid >> 1;
        int d0 = (tid & 1) * 64;
        int pg = p0 + p;
        if (pg >= NP) pg = 0;
        int i0 = pairs[(size_t)pg * 2 + 0];
        int i1 = pairs[(size_t)pg * 2 + 1];
        const float* z0 = &g_z[(size_t)i0 * D + d0];
        const float* z1 = &g_z[(size_t)i1 * D + d0];
#pragma unroll
        for (int t = 0; t < 16; t++) {
            float4 a = *(const float4*)&z0[t * 4];
            float4 b = *(const float4*)&z1[t * 4];
            int k = d0 + t * 4;
            HP[(k + 0) * BP + p] = a.x * b.x;
            HP[(k + 1) * BP + p] = a.y * b.y;
            HP[(k + 2) * BP + p] = a.z * b.z;
            HP[(k + 3) * BP + p] = a.w * b.w;
        }
    }
    float bm1r[8], bm2r[4];
#pragma unroll
    for (int j = 0; j < 8; j++) bm1r[j] = bm1g[tx * 8 + j];
#pragma unroll
    for (int jj = 0; jj < 4; jj++) bm2r[jj] = bm2g[tx * 4 + jj];
    float bm3v = bm3g[0];
    __syncthreads();

    // GEMM1: t1[p][j] = sum_k hp[p][k] * Wm1[j][k]
    float acc1[8][8];
#pragma unroll
    for (int i = 0; i < 8; i++)
#pragma unroll
        for (int j = 0; j < 8; j++) acc1[i][j] = 0.f;

#pragma unroll 8
    for (int k = 0; k < 128; k++) {
        float4 a0 = *(float4*)&HP[k * BP + ty * 8];
        float4 a1 = *(float4*)&HP[k * BP + ty * 8 + 4];
        float4 b0 = *(float4*)&W1s[k * BP + tx * 8];
        float4 b1 = *(float4*)&W1s[k * BP + tx * 8 + 4];
        float a[8] = {a0.x, a0.y, a0.z, a0.w, a1.x, a1.y, a1.z, a1.w};
        float b[8] = {b0.x, b0.y, b0.z, b0.w, b1.x, b1.y, b1.z, b1.w};
#pragma unroll
        for (int i = 0; i < 8; i++)
#pragma unroll
            for (int j = 0; j < 8; j++) acc1[i][j] += a[i] * b[j];
    }
    __syncthreads();

    // write t1 = relu(acc1 + bm1) back into HP, p-major: HP[p*BP + k]
#pragma unroll
    for (int i = 0; i < 8; i++) {
        float o[8];
#pragma unroll
        for (int j = 0; j < 8; j++) o[j] = fmaxf(acc1[i][j] + bm1r[j], 0.f);
        *(float4*)&HP[(ty * 8 + i) * BP + tx * 8]     = make_float4(o[0], o[1], o[2], o[3]);
        *(float4*)&HP[(ty * 8 + i) * BP + tx * 8 + 4] = make_float4(o[4], o[5], o[6], o[7]);
    }
    __syncthreads();

    // GEMM2: t2[p][j2] = sum_k t1[p][k] * Wm2[j2][k],  j2 = tx*4+jj
    float acc2[8][4];
#pragma unroll
    for (int i = 0; i < 8; i++)
#pragma unroll
        for (int jj = 0; jj < 4; jj++) acc2[i][jj] = 0.f;

#pragma unroll 4
    for (int k = 0; k < 128; k++) {
        float a[8];
#pragma unroll
        for (int i = 0; i < 8; i++) a[i] = HP[(ty * 8 + i) * BP + k];
        float4 b = *(float4*)&W2s[k * 64 + tx * 4];
        float bb[4] = {b.x, b.y, b.z, b.w};
#pragma unroll
        for (int i = 0; i < 8; i++)
#pragma unroll
            for (int jj = 0; jj < 4; jj++) acc2[i][jj] += a[i] * bb[jj];
    }

    // stage D: out[p] = sum_j2 relu(t2 + bm2)*wm3 + bm3, reduce across 16 tx lanes
#pragma unroll
    for (int i = 0; i < 8; i++) {
        float part = 0.f;
#pragma unroll
        for (int jj = 0; jj < 4; jj++)
            part += fmaxf(acc2[i][jj] + bm2r[jj], 0.f) * w3s[tx * 4 + jj];
        part += __shfl_xor_sync(0xffffffffu, part, 8);
        part += __shfl_xor_sync(0xffffffffu, part, 4);
        part += __shfl_xor_sync(0xffffffffu, part, 2);
        part += __shfl_xor_sync(0xffffffffu, part, 1);
        if (tx == 0) {
            int p = p0 + ty * 8 + i;
            if (p < NP) out[p] = part + bm3v;
        }
    }
}

// ---------------- launch ----------------
extern "C" void kernel_launch(void* const* d_in, const int* in_sizes, int n_in,
                              void* d_out, int out_size) {
    const float* x     = (const float*)d_in[0];
    const int*   ei    = (const int*)d_in[1];
    const int*   pairs = (const int*)d_in[2];
    const float* W1l = (const float*)d_in[3];
    const float* b1l = (const float*)d_in[4];
    const float* W1r = (const float*)d_in[5];
    const float* W2l = (const float*)d_in[6];
    const float* b2l = (const float*)d_in[7];
    const float* W2r = (const float*)d_in[8];
    const float* Wm1 = (const float*)d_in[9];
    const float* bm1 = (const float*)d_in[10];
    const float* Wm2 = (const float*)d_in[11];
    const float* bm2 = (const float*)d_in[12];
    const float* Wm3 = (const float*)d_in[13];
    const float* bm3 = (const float*)d_in[14];
    float* out = (float*)d_out;

    size_t smem_layer = (size_t)(256 + 32) * BP * sizeof(float);           // 152064
    size_t smem_dec   = (size_t)(128 * BP + 128 * BP + 128 * 64 + 64) * sizeof(float); // 168192
    cudaFuncSetAttribute(k_gemm_layer, cudaFuncAttributeMaxDynamicSharedMemorySize, (int)smem_layer);
    cudaFuncSetAttribute(k_decoder,    cudaFuncAttributeMaxDynamicSharedMemorySize, (int)smem_dec);
    (void)in_sizes; (void)n_in; (void)out_size;

    // CSR build
    k_zero<<<(NN + 255) / 256, 256>>>();
    k_count<<<(NE + 255) / 256, 256>>>(ei);
    k_scan<<<1, 1024>>>();
    k_scatter<<<(NE + 255) / 256, 256>>>(ei);
    k_wt<<<(256 * 128 + 255) / 256, 256>>>(W1l, W1r, W2l, W2r, Wm1, Wm2);

    // layer 1
    k_aggr<<<(NN * 32 + 255) / 256, 256>>>(x, 1);
    k_gemm_layer<<<(NN + 127) / 128, 256, smem_layer>>>(x, b1l, 1);
    // layer 2
    k_aggr<<<(NN * 32 + 255) / 256, 256>>>(x, 2);
    k_gemm_layer<<<(NN + 127) / 128, 256, smem_layer>>>(x, b2l, 2);
    // decoder
    k_decoder<<<(NP + 127) / 128, 256, smem_dec>>>(pairs, bm1, bm2, Wm3, bm3, out);
}